// round 2
// baseline (speedup 1.0000x reference)
#include <cuda_runtime.h>

// Problem constants (fixed by the dataset: x[8,512,8192], CHUNK=16, SE 512->64->512)
#define BB   8
#define CC   512
#define LL   8192
#define CS   16
#define NN   (LL / CS)     // 512 chunk positions
#define CH   (CC / 8)      // 64 bottleneck channels
#define NP   16            // chunk positions handled per block in kernel 2

// Scratch for EMA output e[B, C, N]  (8 MB) — static device global (no allocs).
__device__ float g_e[(size_t)BB * CC * NN];

// ---------------------------------------------------------------------------
// Kernel 1: chunked mean pooling + causal EMA per (b, c) row.
// One block per row (grid = B*C = 4096), 256 threads.
//   phase 1: coalesced float4 stream of 8192 floats -> 512 chunk means in smem
//   phase 2: warp 0 does an affine (A,B) Hillis-Steele scan: y_t = g*y + (1-g)*x_t
// ---------------------------------------------------------------------------
__global__ void __launch_bounds__(256) pool_ema_kernel(
    const float* __restrict__ x, const float* __restrict__ gamma)
{
    const int row = blockIdx.x;            // b*C + c
    const int c   = row & (CC - 1);
    const float g = gamma[c];

    __shared__ float s[NN];                // chunk means

    const float4* xr = reinterpret_cast<const float4*>(x) + (size_t)row * (LL / 4);
    const int t = threadIdx.x;
    // thread t owns chunks 2t and 2t+1 -> float4 indices [t*8, t*8+8)
    float4 v[8];
#pragma unroll
    for (int i = 0; i < 8; i++) v[i] = xr[t * 8 + i];   // 8 LDG.128 in flight

    float sum0 = 0.f, sum1 = 0.f;
#pragma unroll
    for (int i = 0; i < 4; i++)
        sum0 += (v[i].x + v[i].y) + (v[i].z + v[i].w);
#pragma unroll
    for (int i = 4; i < 8; i++)
        sum1 += (v[i].x + v[i].y) + (v[i].z + v[i].w);

    s[2 * t]     = sum0 * (1.0f / 16.0f);
    s[2 * t + 1] = sum1 * (1.0f / 16.0f);
    __syncthreads();

    if (t < 32) {
        const int lane = t;
        const float omg = 1.0f - g;

        // local affine segment over 16 chunk means (init 0): result B, gain A=g^16
        float y = 0.f;
#pragma unroll
        for (int i = 0; i < 16; i++)
            y = fmaf(g, y, omg * s[lane * 16 + i]);
        float Bi = y;
        float g2 = g * g, g4 = g2 * g2, g8 = g4 * g4;
        float Ai = g8 * g8;

        // inclusive scan of affine maps across 32 lanes:
        // combined(x) = self(up(x)) : B' = A*B_up + B ; A' = A*A_up
#pragma unroll
        for (int off = 1; off < 32; off <<= 1) {
            float a_up = __shfl_up_sync(0xffffffffu, Ai, off);
            float b_up = __shfl_up_sync(0xffffffffu, Bi, off);
            if (lane >= off) {
                Bi = fmaf(Ai, b_up, Bi);
                Ai = Ai * a_up;
            }
        }
        // exclusive prefix = inclusive of lane-1 (state entering this lane)
        float prefix = __shfl_up_sync(0xffffffffu, Bi, 1);
        if (lane == 0) prefix = 0.f;

        // replay local segment with the true incoming state, emit e
        float outv[16];
        y = prefix;
#pragma unroll
        for (int i = 0; i < 16; i++) {
            y = fmaf(g, y, omg * s[lane * 16 + i]);
            outv[i] = y;
        }
        float4* er = reinterpret_cast<float4*>(g_e + (size_t)row * NN + lane * 16);
#pragma unroll
        for (int i = 0; i < 4; i++)
            er[i] = make_float4(outv[4 * i], outv[4 * i + 1], outv[4 * i + 2], outv[4 * i + 3]);
    }
}

// ---------------------------------------------------------------------------
// Kernel 2: fused SE bottleneck + sigmoid gate + residual apply.
// Grid: (N/NP = 32, B = 8) = 256 blocks, 256 threads.
// Each block owns (b, chunk positions [n0, n0+NP)):
//   1) load e tile [512][NP] into smem
//   2) h = relu(W1 e + b1)             (64 x NP)
//   3) o = W2 h + b2 ; gate = sigmoid  (512 x NP) -> written back into e smem
//   4) out = gate * x over the 512 x (NP*16) timestep tile (float4 stream)
// ---------------------------------------------------------------------------
__global__ void __launch_bounds__(256) se_apply_kernel(
    const float* __restrict__ x,
    const float* __restrict__ w1, const float* __restrict__ b1,
    const float* __restrict__ w2, const float* __restrict__ b2,
    float* __restrict__ out)
{
    const int b  = blockIdx.y;
    const int n0 = blockIdx.x * NP;
    const int tid = threadIdx.x;

    __shared__ float es[CC][NP];   // 32 KB: e tile, reused for gate
    __shared__ float hs[CH][NP];   // 4 KB

    // ---- 1) load e tile: e[b, c, n0 .. n0+NP) ; 4 float4 per channel row ----
    const float4* ep = reinterpret_cast<const float4*>(
        g_e + ((size_t)b * CC) * NN + n0);
#pragma unroll
    for (int i = 0; i < (CC * NP / 4) / 256; i++) {   // 8 iters
        int idx = tid + i * 256;                      // = c*4 + q
        int cch = idx >> 2, q = idx & 3;
        float4 v = ep[(size_t)cch * (NN / 4) + q];
        *reinterpret_cast<float4*>(&es[cch][q * 4]) = v;
    }
    __syncthreads();

    // ---- 2) h[o][j] : thread = o*4 + q handles j = q*4 .. q*4+3 ----
    {
        const int o = tid >> 2, q = tid & 3;
        float a0 = 0.f, a1 = 0.f, a2 = 0.f, a3 = 0.f;
        const float* wrow = w1 + (size_t)o * CC;
#pragma unroll 4
        for (int cch = 0; cch < CC; cch++) {
            float w = __ldg(wrow + cch);
            float4 ev = *reinterpret_cast<const float4*>(&es[cch][q * 4]);
            a0 = fmaf(w, ev.x, a0);
            a1 = fmaf(w, ev.y, a1);
            a2 = fmaf(w, ev.z, a2);
            a3 = fmaf(w, ev.w, a3);
        }
        const float bb = b1[o];
        hs[o][q * 4 + 0] = fmaxf(a0 + bb, 0.f);
        hs[o][q * 4 + 1] = fmaxf(a1 + bb, 0.f);
        hs[o][q * 4 + 2] = fmaxf(a2 + bb, 0.f);
        hs[o][q * 4 + 3] = fmaxf(a3 + bb, 0.f);
    }
    __syncthreads();

    // ---- 3) gate[cc][j] = sigmoid(W2 h + b2); two channels per thread ----
#pragma unroll
    for (int half = 0; half < 2; half++) {
        const int cch = tid + half * 256;
        float acc[NP];
#pragma unroll
        for (int j = 0; j < NP; j++) acc[j] = 0.f;
        const float* wrow = w2 + (size_t)cch * CH;
#pragma unroll 4
        for (int k = 0; k < CH; k++) {
            float w = __ldg(wrow + k);
#pragma unroll
            for (int j = 0; j < NP; j++)
                acc[j] = fmaf(w, hs[k][j], acc[j]);
        }
        const float bb = b2[cch];
#pragma unroll
        for (int j = 0; j < NP; j++) {
            float o = acc[j] + bb;
            es[cch][j] = 1.0f / (1.0f + expf(-o));   // overwrite e tile with gate
        }
    }
    __syncthreads();

    // ---- 4) out = gate * x over the 512 x (NP*CS) tile, float4 stream ----
    const size_t base = ((size_t)b * CC) * (LL / 4) + (size_t)(n0 * CS) / 4;
    const float4* xp = reinterpret_cast<const float4*>(x) + base;
    float4*       op = reinterpret_cast<float4*>(out) + base;
    const int W = NP * CS / 4;                        // 64 float4 per row
#pragma unroll 8
    for (int i = tid; i < CC * W; i += 256) {
        int r = i >> 6, col = i & (W - 1);
        float gv = es[r][col >> 2];                   // 4 timesteps share one chunk
        float4 v = xp[(size_t)r * (LL / 4) + col];
        v.x *= gv; v.y *= gv; v.z *= gv; v.w *= gv;
        op[(size_t)r * (LL / 4) + col] = v;
    }
}

// ---------------------------------------------------------------------------
// kernel_launch: inputs in metadata order: x, gamma, w1, b1, w2, b2
// ---------------------------------------------------------------------------
extern "C" void kernel_launch(void* const* d_in, const int* in_sizes, int n_in,
                              void* d_out, int out_size)
{
    const float* x     = (const float*)d_in[0];
    const float* gamma = (const float*)d_in[1];
    const float* w1    = (const float*)d_in[2];
    const float* b1    = (const float*)d_in[3];
    const float* w2    = (const float*)d_in[4];
    const float* b2    = (const float*)d_in[5];
    float* out = (float*)d_out;

    pool_ema_kernel<<<BB * CC, 256>>>(x, gamma);

    dim3 grid2(NN / NP, BB);
    se_apply_kernel<<<grid2, 256>>>(x, w1, b1, w2, b2, out);
}

// round 4
// speedup vs baseline: 1.0725x; 1.0725x over previous
#include <cuda_runtime.h>

// Problem constants (x[8,512,8192], CHUNK=16, SE 512->64->512)
#define BB   8
#define CC   512
#define LL   8192
#define CS   16
#define NN   (LL / CS)     // 512 chunk positions
#define CH   (CC / 8)      // 64 bottleneck channels
#define NPG  8             // chunk positions per block in the gate kernel

// Static device scratch (no allocs allowed): EMA output e and gate, 8 MB each.
__device__ float g_e   [(size_t)BB * CC * NN];
__device__ float g_gate[(size_t)BB * CC * NN];

// ---------------------------------------------------------------------------
// Kernel 1: chunked mean pooling + causal EMA per (b, c) row.
// grid = B*C = 4096 blocks, 256 threads.
// ---------------------------------------------------------------------------
__global__ void __launch_bounds__(256) pool_ema_kernel(
    const float* __restrict__ x, const float* __restrict__ gamma)
{
    const int row = blockIdx.x;            // b*C + c
    const int c   = row & (CC - 1);
    const float g = gamma[c];

    __shared__ float s[NN];                // chunk means

    const float4* xr = reinterpret_cast<const float4*>(x) + (size_t)row * (LL / 4);
    const int t = threadIdx.x;
    float4 v[8];
#pragma unroll
    for (int i = 0; i < 8; i++) v[i] = xr[t * 8 + i];   // 8 LDG.128 in flight

    float sum0 = 0.f, sum1 = 0.f;
#pragma unroll
    for (int i = 0; i < 4; i++)
        sum0 += (v[i].x + v[i].y) + (v[i].z + v[i].w);
#pragma unroll
    for (int i = 4; i < 8; i++)
        sum1 += (v[i].x + v[i].y) + (v[i].z + v[i].w);

    s[2 * t]     = sum0 * (1.0f / 16.0f);
    s[2 * t + 1] = sum1 * (1.0f / 16.0f);
    __syncthreads();

    if (t < 32) {
        const int lane = t;
        const float omg = 1.0f - g;

        // local affine segment over 16 chunk means: result Bi, gain Ai = g^16
        float y = 0.f;
#pragma unroll
        for (int i = 0; i < 16; i++)
            y = fmaf(g, y, omg * s[lane * 16 + i]);
        float Bi = y;
        float g2 = g * g, g4 = g2 * g2, g8 = g4 * g4;
        float Ai = g8 * g8;

        // inclusive Hillis-Steele scan of affine maps across 32 lanes
#pragma unroll
        for (int off = 1; off < 32; off <<= 1) {
            float a_up = __shfl_up_sync(0xffffffffu, Ai, off);
            float b_up = __shfl_up_sync(0xffffffffu, Bi, off);
            if (lane >= off) {
                Bi = fmaf(Ai, b_up, Bi);
                Ai = Ai * a_up;
            }
        }
        float prefix = __shfl_up_sync(0xffffffffu, Bi, 1);
        if (lane == 0) prefix = 0.f;

        float outv[16];
        y = prefix;
#pragma unroll
        for (int i = 0; i < 16; i++) {
            y = fmaf(g, y, omg * s[lane * 16 + i]);
            outv[i] = y;
        }
        float4* er = reinterpret_cast<float4*>(g_e + (size_t)row * NN + lane * 16);
#pragma unroll
        for (int i = 0; i < 4; i++)
            er[i] = make_float4(outv[4 * i], outv[4 * i + 1], outv[4 * i + 2], outv[4 * i + 3]);
    }
}

// ---------------------------------------------------------------------------
// Kernel 2: SE bottleneck -> sigmoid gate (small, compute-bound).
// grid (N/NPG = 64, B = 8) = 512 blocks, 256 threads.
// Each block: gate[b, :, n0..n0+NPG) from e[b, :, n0..n0+NPG).
// ---------------------------------------------------------------------------
__global__ void __launch_bounds__(256) se_gate_kernel(
    const float* __restrict__ w1, const float* __restrict__ b1,
    const float* __restrict__ w2, const float* __restrict__ b2)
{
    const int b  = blockIdx.y;
    const int n0 = blockIdx.x * NPG;
    const int tid = threadIdx.x;

    __shared__ float es[CC][NPG];   // 16 KB e tile
    __shared__ float hs[CH][NPG];   // 2 KB hidden

    // ---- load e tile: 2 float4 per channel row; 1024 float4 / 256 thr ----
    const float4* ep = reinterpret_cast<const float4*>(
        g_e + ((size_t)b * CC) * NN + n0);
#pragma unroll
    for (int i = 0; i < 4; i++) {
        int idx = tid + i * 256;                 // = c*2 + q
        int cch = idx >> 1, q = idx & 1;
        float4 v = ep[(size_t)cch * (NN / 4) + q];
        *reinterpret_cast<float4*>(&es[cch][q * 4]) = v;
    }
    __syncthreads();

    // ---- h = relu(W1 e + b1): thread (o = tid>>2, q = tid&3) -> 2 positions ----
    {
        const int o = tid >> 2, q = tid & 3;
        const int j0 = q * 2;
        float a0 = 0.f, a1 = 0.f;
        const float4* wrow = reinterpret_cast<const float4*>(w1 + (size_t)o * CC);
#pragma unroll 2
        for (int cc4 = 0; cc4 < CC / 4; cc4++) {
            float4 w = __ldg(wrow + cc4);
            int cch = cc4 * 4;
            float2 e0 = *reinterpret_cast<const float2*>(&es[cch + 0][j0]);
            float2 e1 = *reinterpret_cast<const float2*>(&es[cch + 1][j0]);
            float2 e2 = *reinterpret_cast<const float2*>(&es[cch + 2][j0]);
            float2 e3 = *reinterpret_cast<const float2*>(&es[cch + 3][j0]);
            a0 = fmaf(w.x, e0.x, a0); a1 = fmaf(w.x, e0.y, a1);
            a0 = fmaf(w.y, e1.x, a0); a1 = fmaf(w.y, e1.y, a1);
            a0 = fmaf(w.z, e2.x, a0); a1 = fmaf(w.z, e2.y, a1);
            a0 = fmaf(w.w, e3.x, a0); a1 = fmaf(w.w, e3.y, a1);
        }
        const float bb = b1[o];
        hs[o][j0 + 0] = fmaxf(a0 + bb, 0.f);
        hs[o][j0 + 1] = fmaxf(a1 + bb, 0.f);
    }
    __syncthreads();

    // ---- gate = sigmoid(W2 h + b2): 2 channels per thread, write to g_gate ----
#pragma unroll
    for (int half = 0; half < 2; half++) {
        const int cch = tid + half * 256;
        float acc[NPG];
#pragma unroll
        for (int j = 0; j < NPG; j++) acc[j] = 0.f;
        const float* wrow = w2 + (size_t)cch * CH;
#pragma unroll 4
        for (int k = 0; k < CH; k++) {
            float w = __ldg(wrow + k);
            float4 h0 = *reinterpret_cast<const float4*>(&hs[k][0]);
            float4 h1 = *reinterpret_cast<const float4*>(&hs[k][4]);
            acc[0] = fmaf(w, h0.x, acc[0]); acc[1] = fmaf(w, h0.y, acc[1]);
            acc[2] = fmaf(w, h0.z, acc[2]); acc[3] = fmaf(w, h0.w, acc[3]);
            acc[4] = fmaf(w, h1.x, acc[4]); acc[5] = fmaf(w, h1.y, acc[5]);
            acc[6] = fmaf(w, h1.z, acc[6]); acc[7] = fmaf(w, h1.w, acc[7]);
        }
        const float bb = b2[cch];
        float4 o0, o1;
        o0.x = 1.0f / (1.0f + __expf(-(acc[0] + bb)));
        o0.y = 1.0f / (1.0f + __expf(-(acc[1] + bb)));
        o0.z = 1.0f / (1.0f + __expf(-(acc[2] + bb)));
        o0.w = 1.0f / (1.0f + __expf(-(acc[3] + bb)));
        o1.x = 1.0f / (1.0f + __expf(-(acc[4] + bb)));
        o1.y = 1.0f / (1.0f + __expf(-(acc[5] + bb)));
        o1.z = 1.0f / (1.0f + __expf(-(acc[6] + bb)));
        o1.w = 1.0f / (1.0f + __expf(-(acc[7] + bb)));
        float4* gp = reinterpret_cast<float4*>(
            g_gate + ((size_t)b * CC + cch) * NN + n0);
        gp[0] = o0;
        gp[1] = o1;
    }
}

// ---------------------------------------------------------------------------
// Kernel 3: out = gate * x, pure stream. One block per (b,c) row:
// grid = 4096 blocks, 256 threads, 8 front-batched LDG.128 per thread.
// ---------------------------------------------------------------------------
__global__ void __launch_bounds__(256) apply_kernel(
    const float* __restrict__ x, float* __restrict__ out)
{
    const int row = blockIdx.x;                       // b*C + c
    const int t = threadIdx.x;

    __shared__ float gs[NN];                          // this row's 512 gate values

    // stage gate row (512 floats) via 128 float4 loads
    if (t < 128) {
        const float4* gp = reinterpret_cast<const float4*>(g_gate + (size_t)row * NN);
        *reinterpret_cast<float4*>(&gs[t * 4]) = gp[t];
    }
    __syncthreads();

    const float4* xr = reinterpret_cast<const float4*>(x)   + (size_t)row * (LL / 4);
    float4*       orr = reinterpret_cast<float4*>(out)      + (size_t)row * (LL / 4);

    float4 v[8];
#pragma unroll
    for (int k = 0; k < 8; k++)
        v[k] = xr[t + k * 256];                       // 8 LDG.128 in flight
#pragma unroll
    for (int k = 0; k < 8; k++) {
        int f = t + k * 256;
        float gv = gs[f >> 2];                        // 4 float4 per chunk
        v[k].x *= gv; v[k].y *= gv; v[k].z *= gv; v[k].w *= gv;
        orr[f] = v[k];
    }
}

// ---------------------------------------------------------------------------
// kernel_launch: inputs in metadata order: x, gamma, w1, b1, w2, b2
// ---------------------------------------------------------------------------
extern "C" void kernel_launch(void* const* d_in, const int* in_sizes, int n_in,
                              void* d_out, int out_size)
{
    const float* x     = (const float*)d_in[0];
    const float* gamma = (const float*)d_in[1];
    const float* w1    = (const float*)d_in[2];
    const float* b1    = (const float*)d_in[3];
    const float* w2    = (const float*)d_in[4];
    const float* b2    = (const float*)d_in[5];
    float* out = (float*)d_out;

    pool_ema_kernel<<<BB * CC, 256>>>(x, gamma);

    dim3 gridG(NN / NPG, BB);
    se_gate_kernel<<<gridG, 256>>>(w1, b1, w2, b2);

    apply_kernel<<<BB * CC, 256>>>(x, out);
}

// round 7
// speedup vs baseline: 1.1064x; 1.0316x over previous
#include <cuda_runtime.h>

// Problem constants (x[8,512,8192], CHUNK=16, SE 512->64->512)
#define BB   8
#define CC   512
#define LL   8192
#define CS   16
#define NN   (LL / CS)     // 512 chunk positions
#define CH   (CC / 8)      // 64 bottleneck channels
#define NPG  8             // chunk positions per block in the gate kernel

// Static device scratch (no allocs allowed): EMA output e and gate, 8 MB each.
__device__ float g_e   [(size_t)BB * CC * NN];
__device__ float g_gate[(size_t)BB * CC * NN];

// ---------------------------------------------------------------------------
// Kernel 1: chunked mean pooling + causal EMA per (b, c) row.
// grid = B*C = 4096 blocks, 256 threads. Default cache policy: we WANT x to
// stay resident in L2 so the (reversed) apply kernel hits it.
// ---------------------------------------------------------------------------
__global__ void __launch_bounds__(256) pool_ema_kernel(
    const float* __restrict__ x, const float* __restrict__ gamma)
{
    const int row = blockIdx.x;            // b*C + c
    const int c   = row & (CC - 1);
    const float g = gamma[c];

    __shared__ float s[NN];                // chunk means

    const float4* xr = reinterpret_cast<const float4*>(x) + (size_t)row * (LL / 4);
    const int t = threadIdx.x;
    float4 v[8];
#pragma unroll
    for (int i = 0; i < 8; i++) v[i] = xr[t * 8 + i];   // 8 LDG.128 in flight

    float sum0 = 0.f, sum1 = 0.f;
#pragma unroll
    for (int i = 0; i < 4; i++)
        sum0 += (v[i].x + v[i].y) + (v[i].z + v[i].w);
#pragma unroll
    for (int i = 4; i < 8; i++)
        sum1 += (v[i].x + v[i].y) + (v[i].z + v[i].w);

    s[2 * t]     = sum0 * (1.0f / 16.0f);
    s[2 * t + 1] = sum1 * (1.0f / 16.0f);
    __syncthreads();

    if (t < 32) {
        const int lane = t;
        const float omg = 1.0f - g;

        // local affine segment over 16 chunk means: result Bi, gain Ai = g^16
        float y = 0.f;
#pragma unroll
        for (int i = 0; i < 16; i++)
            y = fmaf(g, y, omg * s[lane * 16 + i]);
        float Bi = y;
        float g2 = g * g, g4 = g2 * g2, g8 = g4 * g4;
        float Ai = g8 * g8;

        // inclusive Hillis-Steele scan of affine maps across 32 lanes
#pragma unroll
        for (int off = 1; off < 32; off <<= 1) {
            float a_up = __shfl_up_sync(0xffffffffu, Ai, off);
            float b_up = __shfl_up_sync(0xffffffffu, Bi, off);
            if (lane >= off) {
                Bi = fmaf(Ai, b_up, Bi);
                Ai = Ai * a_up;
            }
        }
        float prefix = __shfl_up_sync(0xffffffffu, Bi, 1);
        if (lane == 0) prefix = 0.f;

        float outv[16];
        y = prefix;
#pragma unroll
        for (int i = 0; i < 16; i++) {
            y = fmaf(g, y, omg * s[lane * 16 + i]);
            outv[i] = y;
        }
        float4* er = reinterpret_cast<float4*>(g_e + (size_t)row * NN + lane * 16);
#pragma unroll
        for (int i = 0; i < 4; i++)
            er[i] = make_float4(outv[4 * i], outv[4 * i + 1], outv[4 * i + 2], outv[4 * i + 3]);
    }
}

// ---------------------------------------------------------------------------
// Kernel 2: SE bottleneck -> sigmoid gate (small, compute-bound).
// grid (N/NPG = 64, B = 8) = 512 blocks, 256 threads.
// e reads use __ldcs (read-once, evict-first) to protect x's L2 residency.
// ---------------------------------------------------------------------------
__global__ void __launch_bounds__(256) se_gate_kernel(
    const float* __restrict__ w1, const float* __restrict__ b1,
    const float* __restrict__ w2, const float* __restrict__ b2)
{
    const int b  = blockIdx.y;
    const int n0 = blockIdx.x * NPG;
    const int tid = threadIdx.x;

    __shared__ float es[CC][NPG];   // 16 KB e tile
    __shared__ float hs[CH][NPG];   // 2 KB hidden

    // ---- load e tile: 2 float4 per channel row; 1024 float4 / 256 thr ----
    const float4* ep = reinterpret_cast<const float4*>(
        g_e + ((size_t)b * CC) * NN + n0);
#pragma unroll
    for (int i = 0; i < 4; i++) {
        int idx = tid + i * 256;                 // = c*2 + q
        int cch = idx >> 1, q = idx & 1;
        float4 v = __ldcs(ep + (size_t)cch * (NN / 4) + q);
        *reinterpret_cast<float4*>(&es[cch][q * 4]) = v;
    }
    __syncthreads();

    // ---- h = relu(W1 e + b1): thread (o = tid>>2, q = tid&3) -> 2 positions ----
    {
        const int o = tid >> 2, q = tid & 3;
        const int j0 = q * 2;
        float a0 = 0.f, a1 = 0.f;
        const float4* wrow = reinterpret_cast<const float4*>(w1 + (size_t)o * CC);
#pragma unroll 2
        for (int cc4 = 0; cc4 < CC / 4; cc4++) {
            float4 w = __ldg(wrow + cc4);
            int cch = cc4 * 4;
            float2 e0 = *reinterpret_cast<const float2*>(&es[cch + 0][j0]);
            float2 e1 = *reinterpret_cast<const float2*>(&es[cch + 1][j0]);
            float2 e2 = *reinterpret_cast<const float2*>(&es[cch + 2][j0]);
            float2 e3 = *reinterpret_cast<const float2*>(&es[cch + 3][j0]);
            a0 = fmaf(w.x, e0.x, a0); a1 = fmaf(w.x, e0.y, a1);
            a0 = fmaf(w.y, e1.x, a0); a1 = fmaf(w.y, e1.y, a1);
            a0 = fmaf(w.z, e2.x, a0); a1 = fmaf(w.z, e2.y, a1);
            a0 = fmaf(w.w, e3.x, a0); a1 = fmaf(w.w, e3.y, a1);
        }
        const float bb = b1[o];
        hs[o][j0 + 0] = fmaxf(a0 + bb, 0.f);
        hs[o][j0 + 1] = fmaxf(a1 + bb, 0.f);
    }
    __syncthreads();

    // ---- gate = sigmoid(W2 h + b2): 2 channels per thread, write to g_gate ----
#pragma unroll
    for (int half = 0; half < 2; half++) {
        const int cch = tid + half * 256;
        float acc[NPG];
#pragma unroll
        for (int j = 0; j < NPG; j++) acc[j] = 0.f;
        const float* wrow = w2 + (size_t)cch * CH;
#pragma unroll 4
        for (int k = 0; k < CH; k++) {
            float w = __ldg(wrow + k);
            float4 h0 = *reinterpret_cast<const float4*>(&hs[k][0]);
            float4 h1 = *reinterpret_cast<const float4*>(&hs[k][4]);
            acc[0] = fmaf(w, h0.x, acc[0]); acc[1] = fmaf(w, h0.y, acc[1]);
            acc[2] = fmaf(w, h0.z, acc[2]); acc[3] = fmaf(w, h0.w, acc[3]);
            acc[4] = fmaf(w, h1.x, acc[4]); acc[5] = fmaf(w, h1.y, acc[5]);
            acc[6] = fmaf(w, h1.z, acc[6]); acc[7] = fmaf(w, h1.w, acc[7]);
        }
        const float bb = b2[cch];
        float4 o0, o1;
        o0.x = 1.0f / (1.0f + __expf(-(acc[0] + bb)));
        o0.y = 1.0f / (1.0f + __expf(-(acc[1] + bb)));
        o0.z = 1.0f / (1.0f + __expf(-(acc[2] + bb)));
        o0.w = 1.0f / (1.0f + __expf(-(acc[3] + bb)));
        o1.x = 1.0f / (1.0f + __expf(-(acc[4] + bb)));
        o1.y = 1.0f / (1.0f + __expf(-(acc[5] + bb)));
        o1.z = 1.0f / (1.0f + __expf(-(acc[6] + bb)));
        o1.w = 1.0f / (1.0f + __expf(-(acc[7] + bb)));
        float4* gp = reinterpret_cast<float4*>(
            g_gate + ((size_t)b * CC + cch) * NN + n0);
        gp[0] = o0;
        gp[1] = o1;
    }
}

// ---------------------------------------------------------------------------
// Kernel 3: out = gate * x, pure stream.
// grid = 4096 blocks, 256 threads. ROW ORDER REVERSED vs pool so the first
// waves read the x rows still resident in L2 (x is 128MB vs 126MB L2).
// x loads are evict-first (__ldcs: read-once), out stores streaming (__stcs)
// so they don't evict x lines not yet read.
// ---------------------------------------------------------------------------
__global__ void __launch_bounds__(256) apply_kernel(
    const float* __restrict__ x, float* __restrict__ out)
{
    const int row = (BB * CC - 1) - blockIdx.x;       // reversed traversal
    const int t = threadIdx.x;

    __shared__ float gs[NN];                          // this row's 512 gate values

    // stage gate row (512 floats) via 128 float4 loads
    if (t < 128) {
        const float4* gp = reinterpret_cast<const float4*>(g_gate + (size_t)row * NN);
        *reinterpret_cast<float4*>(&gs[t * 4]) = gp[t];
    }
    __syncthreads();

    const float4* xr  = reinterpret_cast<const float4*>(x)   + (size_t)row * (LL / 4);
    float4*       orr = reinterpret_cast<float4*>(out)       + (size_t)row * (LL / 4);

    float4 v[8];
#pragma unroll
    for (int k = 0; k < 8; k++)
        v[k] = __ldcs(xr + t + k * 256);              // 8 LDG.128.CS in flight
#pragma unroll
    for (int k = 0; k < 8; k++) {
        int f = t + k * 256;
        float gv = gs[f >> 2];                        // 4 float4 per chunk
        v[k].x *= gv; v[k].y *= gv; v[k].z *= gv; v[k].w *= gv;
        __stcs(orr + f, v[k]);
    }
}

// ---------------------------------------------------------------------------
// kernel_launch: inputs in metadata order: x, gamma, w1, b1, w2, b2
// ---------------------------------------------------------------------------
extern "C" void kernel_launch(void* const* d_in, const int* in_sizes, int n_in,
                              void* d_out, int out_size)
{
    const float* x     = (const float*)d_in[0];
    const float* gamma = (const float*)d_in[1];
    const float* w1    = (const float*)d_in[2];
    const float* b1    = (const float*)d_in[3];
    const float* w2    = (const float*)d_in[4];
    const float* b2    = (const float*)d_in[5];
    float* out = (float*)d_out;

    pool_ema_kernel<<<BB * CC, 256>>>(x, gamma);

    dim3 gridG(NN / NPG, BB);
    se_gate_kernel<<<gridG, 256>>>(w1, b1, w2, b2);

    apply_kernel<<<BB * CC, 256>>>(x, out);
}

// round 8
// speedup vs baseline: 1.1758x; 1.0627x over previous
#include <cuda_runtime.h>

// Problem constants (x[8,512,8192], CHUNK=16, SE 512->64->512)
#define BB   8
#define CC   512
#define LL   8192
#define CS   16
#define NN   (LL / CS)     // 512 chunk positions
#define CH   (CC / 8)      // 64 bottleneck channels
#define NPG  8             // chunk positions per block in the gate kernel

// Static device scratch (no allocs allowed): EMA output e and gate, 8 MB each.
__device__ float g_e   [(size_t)BB * CC * NN];
__device__ float g_gate[(size_t)BB * CC * NN];

// padded smem index: lane stride becomes 17 banks (conflict-free)
#define SPAD(i) ((i) + ((i) >> 4))

// ---------------------------------------------------------------------------
// Kernel 1: chunked mean pooling + causal EMA per (b, c) row.
// grid = B*C = 4096 blocks, 256 threads.
// COALESCED: thread t loads xr[t + k*256] (unit lane stride -> 4 wf/warp-LDG).
// Each float4 lies inside one chunk; 4-lane shfl groups form chunk sums.
// ---------------------------------------------------------------------------
__global__ void __launch_bounds__(256) pool_ema_kernel(
    const float* __restrict__ x, const float* __restrict__ gamma)
{
    const int row = blockIdx.x;            // b*C + c
    const int c   = row & (CC - 1);
    const float g = gamma[c];

    __shared__ float s[NN + NN / 16];      // padded chunk means

    const float4* xr = reinterpret_cast<const float4*>(x) + (size_t)row * (LL / 4);
    const int t = threadIdx.x;

    float4 v[8];
#pragma unroll
    for (int k = 0; k < 8; k++)
        v[k] = xr[t + k * 256];            // 8 coalesced LDG.128 in flight

#pragma unroll
    for (int k = 0; k < 8; k++) {
        float r = (v[k].x + v[k].y) + (v[k].z + v[k].w);
        // reduce across the 4 lanes holding the same chunk (width=4 segments)
        r += __shfl_down_sync(0xffffffffu, r, 2, 4);
        r += __shfl_down_sync(0xffffffffu, r, 1, 4);
        if ((t & 3) == 0) {
            int ci = (t >> 2) + k * 64;    // chunk index 0..511
            s[SPAD(ci)] = r * (1.0f / 16.0f);
        }
    }
    __syncthreads();

    if (t < 32) {
        const int lane = t;
        const float omg = 1.0f - g;

        // local affine segment over 16 chunk means: result Bi, gain Ai = g^16
        float y = 0.f;
#pragma unroll
        for (int i = 0; i < 16; i++)
            y = fmaf(g, y, omg * s[lane * 17 + i]);      // SPAD(lane*16+i)
        float Bi = y;
        float g2 = g * g, g4 = g2 * g2, g8 = g4 * g4;
        float Ai = g8 * g8;

        // inclusive Hillis-Steele scan of affine maps across 32 lanes
#pragma unroll
        for (int off = 1; off < 32; off <<= 1) {
            float a_up = __shfl_up_sync(0xffffffffu, Ai, off);
            float b_up = __shfl_up_sync(0xffffffffu, Bi, off);
            if (lane >= off) {
                Bi = fmaf(Ai, b_up, Bi);
                Ai = Ai * a_up;
            }
        }
        float prefix = __shfl_up_sync(0xffffffffu, Bi, 1);
        if (lane == 0) prefix = 0.f;

        float outv[16];
        y = prefix;
#pragma unroll
        for (int i = 0; i < 16; i++) {
            y = fmaf(g, y, omg * s[lane * 17 + i]);
            outv[i] = y;
        }
        float4* er = reinterpret_cast<float4*>(g_e + (size_t)row * NN + lane * 16);
#pragma unroll
        for (int i = 0; i < 4; i++)
            er[i] = make_float4(outv[4 * i], outv[4 * i + 1], outv[4 * i + 2], outv[4 * i + 3]);
    }
}

// ---------------------------------------------------------------------------
// Kernel 2: SE bottleneck -> sigmoid gate (small, compute-bound).
// grid (N/NPG = 64, B = 8) = 512 blocks, 256 threads.
// ---------------------------------------------------------------------------
__global__ void __launch_bounds__(256) se_gate_kernel(
    const float* __restrict__ w1, const float* __restrict__ b1,
    const float* __restrict__ w2, const float* __restrict__ b2)
{
    const int b  = blockIdx.y;
    const int n0 = blockIdx.x * NPG;
    const int tid = threadIdx.x;

    __shared__ float es[CC][NPG];   // 16 KB e tile
    __shared__ float hs[CH][NPG];   // 2 KB hidden

    // ---- load e tile: 2 float4 per channel row; 1024 float4 / 256 thr ----
    const float4* ep = reinterpret_cast<const float4*>(
        g_e + ((size_t)b * CC) * NN + n0);
#pragma unroll
    for (int i = 0; i < 4; i++) {
        int idx = tid + i * 256;                 // = c*2 + q
        int cch = idx >> 1, q = idx & 1;
        float4 v = __ldcs(ep + (size_t)cch * (NN / 4) + q);
        *reinterpret_cast<float4*>(&es[cch][q * 4]) = v;
    }
    __syncthreads();

    // ---- h = relu(W1 e + b1): thread (o = tid>>2, q = tid&3) -> 2 positions ----
    {
        const int o = tid >> 2, q = tid & 3;
        const int j0 = q * 2;
        float a0 = 0.f, a1 = 0.f;
        const float4* wrow = reinterpret_cast<const float4*>(w1 + (size_t)o * CC);
#pragma unroll 2
        for (int cc4 = 0; cc4 < CC / 4; cc4++) {
            float4 w = __ldg(wrow + cc4);
            int cch = cc4 * 4;
            float2 e0 = *reinterpret_cast<const float2*>(&es[cch + 0][j0]);
            float2 e1 = *reinterpret_cast<const float2*>(&es[cch + 1][j0]);
            float2 e2 = *reinterpret_cast<const float2*>(&es[cch + 2][j0]);
            float2 e3 = *reinterpret_cast<const float2*>(&es[cch + 3][j0]);
            a0 = fmaf(w.x, e0.x, a0); a1 = fmaf(w.x, e0.y, a1);
            a0 = fmaf(w.y, e1.x, a0); a1 = fmaf(w.y, e1.y, a1);
            a0 = fmaf(w.z, e2.x, a0); a1 = fmaf(w.z, e2.y, a1);
            a0 = fmaf(w.w, e3.x, a0); a1 = fmaf(w.w, e3.y, a1);
        }
        const float bb = b1[o];
        hs[o][j0 + 0] = fmaxf(a0 + bb, 0.f);
        hs[o][j0 + 1] = fmaxf(a1 + bb, 0.f);
    }
    __syncthreads();

    // ---- gate = sigmoid(W2 h + b2): 2 channels per thread, write to g_gate ----
#pragma unroll
    for (int half = 0; half < 2; half++) {
        const int cch = tid + half * 256;
        float acc[NPG];
#pragma unroll
        for (int j = 0; j < NPG; j++) acc[j] = 0.f;
        const float* wrow = w2 + (size_t)cch * CH;
#pragma unroll 4
        for (int k = 0; k < CH; k++) {
            float w = __ldg(wrow + k);
            float4 h0 = *reinterpret_cast<const float4*>(&hs[k][0]);
            float4 h1 = *reinterpret_cast<const float4*>(&hs[k][4]);
            acc[0] = fmaf(w, h0.x, acc[0]); acc[1] = fmaf(w, h0.y, acc[1]);
            acc[2] = fmaf(w, h0.z, acc[2]); acc[3] = fmaf(w, h0.w, acc[3]);
            acc[4] = fmaf(w, h1.x, acc[4]); acc[5] = fmaf(w, h1.y, acc[5]);
            acc[6] = fmaf(w, h1.z, acc[6]); acc[7] = fmaf(w, h1.w, acc[7]);
        }
        const float bb = b2[cch];
        float4 o0, o1;
        o0.x = 1.0f / (1.0f + __expf(-(acc[0] + bb)));
        o0.y = 1.0f / (1.0f + __expf(-(acc[1] + bb)));
        o0.z = 1.0f / (1.0f + __expf(-(acc[2] + bb)));
        o0.w = 1.0f / (1.0f + __expf(-(acc[3] + bb)));
        o1.x = 1.0f / (1.0f + __expf(-(acc[4] + bb)));
        o1.y = 1.0f / (1.0f + __expf(-(acc[5] + bb)));
        o1.z = 1.0f / (1.0f + __expf(-(acc[6] + bb)));
        o1.w = 1.0f / (1.0f + __expf(-(acc[7] + bb)));
        float4* gp = reinterpret_cast<float4*>(
            g_gate + ((size_t)b * CC + cch) * NN + n0);
        gp[0] = o0;
        gp[1] = o1;
    }
}

// ---------------------------------------------------------------------------
// Kernel 3: out = gate * x, pure stream (coalesced).
// grid = 4096 blocks reversed vs pool; x read-once (__ldcs), out streaming.
// ---------------------------------------------------------------------------
__global__ void __launch_bounds__(256) apply_kernel(
    const float* __restrict__ x, float* __restrict__ out)
{
    const int row = (BB * CC - 1) - blockIdx.x;       // reversed traversal
    const int t = threadIdx.x;

    __shared__ float gs[NN];                          // this row's 512 gate values

    if (t < 128) {
        const float4* gp = reinterpret_cast<const float4*>(g_gate + (size_t)row * NN);
        *reinterpret_cast<float4*>(&gs[t * 4]) = gp[t];
    }
    __syncthreads();

    const float4* xr  = reinterpret_cast<const float4*>(x)   + (size_t)row * (LL / 4);
    float4*       orr = reinterpret_cast<float4*>(out)       + (size_t)row * (LL / 4);

    float4 v[8];
#pragma unroll
    for (int k = 0; k < 8; k++)
        v[k] = __ldcs(xr + t + k * 256);              // 8 LDG.128.CS in flight
#pragma unroll
    for (int k = 0; k < 8; k++) {
        int f = t + k * 256;
        float gv = gs[f >> 2];                        // 4 float4 per chunk
        v[k].x *= gv; v[k].y *= gv; v[k].z *= gv; v[k].w *= gv;
        __stcs(orr + f, v[k]);
    }
}

// ---------------------------------------------------------------------------
// kernel_launch: inputs in metadata order: x, gamma, w1, b1, w2, b2
// ---------------------------------------------------------------------------
extern "C" void kernel_launch(void* const* d_in, const int* in_sizes, int n_in,
                              void* d_out, int out_size)
{
    const float* x     = (const float*)d_in[0];
    const float* gamma = (const float*)d_in[1];
    const float* w1    = (const float*)d_in[2];
    const float* b1    = (const float*)d_in[3];
    const float* w2    = (const float*)d_in[4];
    const float* b2    = (const float*)d_in[5];
    float* out = (float*)d_out;

    pool_ema_kernel<<<BB * CC, 256>>>(x, gamma);

    dim3 gridG(NN / NPG, BB);
    se_gate_kernel<<<gridG, 256>>>(w1, b1, w2, b2);

    apply_kernel<<<BB * CC, 256>>>(x, out);
}

// round 9
// speedup vs baseline: 1.8792x; 1.5982x over previous
#include <cuda_runtime.h>

// Problem constants (x[8,512,8192], CHUNK=16, SE 512->64->512)
#define BB   8
#define CC   512
#define LL   8192
#define CS   16
#define NN   (LL / CS)     // 512 chunk positions
#define CH   (CC / 8)      // 64 bottleneck channels
#define NPG  8             // chunk positions per block in the gate kernel

// Static device scratch (no allocs allowed).
__device__ float g_e   [(size_t)BB * CC * NN];   // EMA output, 8 MB
__device__ float g_gate[(size_t)BB * CC * NN];   // gate, 8 MB
__device__ float g_w1t [(size_t)CC * CH];        // w1 transposed [c][o], 128 KB
__device__ float g_w2t [(size_t)CH * CC];        // w2 transposed [k][c], 128 KB

// padded smem index: lane stride becomes 17 banks (conflict-free)
#define SPAD(i) ((i) + ((i) >> 4))

// ---------------------------------------------------------------------------
// Kernel 0: transpose weights so GEMM loads are lane-coalesced.
// w1 [CH][CC] -> w1t [CC][CH];  w2 [CC][CH] -> w2t [CH][CC].  32768 elems each.
// ---------------------------------------------------------------------------
__global__ void __launch_bounds__(256) transpose_w_kernel(
    const float* __restrict__ w1, const float* __restrict__ w2)
{
    const int i = blockIdx.x * 256 + threadIdx.x;   // 0 .. 32767
    {   // w1: read coalesced (o-major), scatter write
        int o = i / CC, c = i % CC;
        g_w1t[(size_t)c * CH + o] = w1[i];
    }
    {   // w2: read coalesced (c-major), scatter write
        int c = i / CH, k = i % CH;
        g_w2t[(size_t)k * CC + c] = w2[i];
    }
}

// ---------------------------------------------------------------------------
// Kernel 1: chunked mean pooling + causal EMA per (b, c) row.
// grid = B*C = 4096 blocks, 256 threads. Coalesced; 4-lane shfl chunk sums.
// ---------------------------------------------------------------------------
__global__ void __launch_bounds__(256) pool_ema_kernel(
    const float* __restrict__ x, const float* __restrict__ gamma)
{
    const int row = blockIdx.x;            // b*C + c
    const int c   = row & (CC - 1);
    const float g = gamma[c];

    __shared__ float s[NN + NN / 16];      // padded chunk means

    const float4* xr = reinterpret_cast<const float4*>(x) + (size_t)row * (LL / 4);
    const int t = threadIdx.x;

    float4 v[8];
#pragma unroll
    for (int k = 0; k < 8; k++)
        v[k] = xr[t + k * 256];            // 8 coalesced LDG.128 in flight

#pragma unroll
    for (int k = 0; k < 8; k++) {
        float r = (v[k].x + v[k].y) + (v[k].z + v[k].w);
        r += __shfl_down_sync(0xffffffffu, r, 2, 4);
        r += __shfl_down_sync(0xffffffffu, r, 1, 4);
        if ((t & 3) == 0) {
            int ci = (t >> 2) + k * 64;    // chunk index 0..511
            s[SPAD(ci)] = r * (1.0f / 16.0f);
        }
    }
    __syncthreads();

    if (t < 32) {
        const int lane = t;
        const float omg = 1.0f - g;

        float y = 0.f;
#pragma unroll
        for (int i = 0; i < 16; i++)
            y = fmaf(g, y, omg * s[lane * 17 + i]);      // SPAD(lane*16+i)
        float Bi = y;
        float g2 = g * g, g4 = g2 * g2, g8 = g4 * g4;
        float Ai = g8 * g8;

#pragma unroll
        for (int off = 1; off < 32; off <<= 1) {
            float a_up = __shfl_up_sync(0xffffffffu, Ai, off);
            float b_up = __shfl_up_sync(0xffffffffu, Bi, off);
            if (lane >= off) {
                Bi = fmaf(Ai, b_up, Bi);
                Ai = Ai * a_up;
            }
        }
        float prefix = __shfl_up_sync(0xffffffffu, Bi, 1);
        if (lane == 0) prefix = 0.f;

        float outv[16];
        y = prefix;
#pragma unroll
        for (int i = 0; i < 16; i++) {
            y = fmaf(g, y, omg * s[lane * 17 + i]);
            outv[i] = y;
        }
        float4* er = reinterpret_cast<float4*>(g_e + (size_t)row * NN + lane * 16);
#pragma unroll
        for (int i = 0; i < 4; i++)
            er[i] = make_float4(outv[4 * i], outv[4 * i + 1], outv[4 * i + 2], outv[4 * i + 3]);
    }
}

// ---------------------------------------------------------------------------
// Kernel 2: SE bottleneck -> sigmoid gate, using TRANSPOSED weights so every
// weight LDG is lane-coalesced (1-4 wavefronts instead of 8-32).
// grid (N/NPG = 64, B = 8) = 512 blocks, 256 threads.
// ---------------------------------------------------------------------------
__global__ void __launch_bounds__(256) se_gate_kernel(
    const float* __restrict__ b1, const float* __restrict__ b2)
{
    const int b  = blockIdx.y;
    const int n0 = blockIdx.x * NPG;
    const int tid = threadIdx.x;

    __shared__ float es[CC][NPG];   // 16 KB e tile
    __shared__ float hs[CH][NPG];   // 2 KB hidden

    // ---- load e tile: 2 float4 per channel row; 1024 float4 / 256 thr ----
    const float4* ep = reinterpret_cast<const float4*>(
        g_e + ((size_t)b * CC) * NN + n0);
#pragma unroll
    for (int i = 0; i < 4; i++) {
        int idx = tid + i * 256;                 // = c*2 + q
        int cch = idx >> 1, q = idx & 1;
        float4 v = __ldcs(ep + (size_t)cch * (NN / 4) + q);
        *reinterpret_cast<float4*>(&es[cch][q * 4]) = v;
    }
    __syncthreads();

    // ---- h = relu(W1 e + b1): thread (o = tid>>2, q = tid&3) -> 2 positions
    //      weight load w1t[cc][o]: 8 consecutive floats per warp -> 1 sector
    {
        const int o = tid >> 2, q = tid & 3;
        const int j0 = q * 2;
        float a0 = 0.f, a1 = 0.f;
#pragma unroll 8
        for (int cc = 0; cc < CC; cc++) {
            float w = __ldg(g_w1t + (size_t)cc * CH + o);
            float2 e = *reinterpret_cast<const float2*>(&es[cc][j0]);
            a0 = fmaf(w, e.x, a0);
            a1 = fmaf(w, e.y, a1);
        }
        const float bb = b1[o];
        hs[o][j0 + 0] = fmaxf(a0 + bb, 0.f);
        hs[o][j0 + 1] = fmaxf(a1 + bb, 0.f);
    }
    __syncthreads();

    // ---- gate = sigmoid(W2 h + b2): 2 channels per thread
    //      weight load w2t[k][cch]: 32 consecutive floats per warp -> 1 line
#pragma unroll
    for (int half = 0; half < 2; half++) {
        const int cch = tid + half * 256;
        float acc[NPG];
#pragma unroll
        for (int j = 0; j < NPG; j++) acc[j] = 0.f;
#pragma unroll 8
        for (int k = 0; k < CH; k++) {
            float w = __ldg(g_w2t + (size_t)k * CC + cch);
            float4 h0 = *reinterpret_cast<const float4*>(&hs[k][0]);
            float4 h1 = *reinterpret_cast<const float4*>(&hs[k][4]);
            acc[0] = fmaf(w, h0.x, acc[0]); acc[1] = fmaf(w, h0.y, acc[1]);
            acc[2] = fmaf(w, h0.z, acc[2]); acc[3] = fmaf(w, h0.w, acc[3]);
            acc[4] = fmaf(w, h1.x, acc[4]); acc[5] = fmaf(w, h1.y, acc[5]);
            acc[6] = fmaf(w, h1.z, acc[6]); acc[7] = fmaf(w, h1.w, acc[7]);
        }
        const float bb = b2[cch];
        float4 o0, o1;
        o0.x = 1.0f / (1.0f + __expf(-(acc[0] + bb)));
        o0.y = 1.0f / (1.0f + __expf(-(acc[1] + bb)));
        o0.z = 1.0f / (1.0f + __expf(-(acc[2] + bb)));
        o0.w = 1.0f / (1.0f + __expf(-(acc[3] + bb)));
        o1.x = 1.0f / (1.0f + __expf(-(acc[4] + bb)));
        o1.y = 1.0f / (1.0f + __expf(-(acc[5] + bb)));
        o1.z = 1.0f / (1.0f + __expf(-(acc[6] + bb)));
        o1.w = 1.0f / (1.0f + __expf(-(acc[7] + bb)));
        float4* gp = reinterpret_cast<float4*>(
            g_gate + ((size_t)b * CC + cch) * NN + n0);
        gp[0] = o0;
        gp[1] = o1;
    }
}

// ---------------------------------------------------------------------------
// Kernel 3: out = gate * x, barrier-free pure stream.
// grid = 4096 blocks reversed vs pool. Per k-step each warp loads the 8 gate
// chunks it needs (1-sector LDG.32) and distributes via shfl — no smem stage.
// x read-once (__ldcs), out streaming (__stcs).
// ---------------------------------------------------------------------------
__global__ void __launch_bounds__(256) apply_kernel(
    const float* __restrict__ x, float* __restrict__ out)
{
    const int row  = (BB * CC - 1) - blockIdx.x;      // reversed traversal
    const int t    = threadIdx.x;
    const int warp = t >> 5, lane = t & 31;

    const float* grow = g_gate + (size_t)row * NN;
    const float4* xr  = reinterpret_cast<const float4*>(x)  + (size_t)row * (LL / 4);
    float4*       orr = reinterpret_cast<float4*>(out)      + (size_t)row * (LL / 4);

    // front-batch: 8 x-loads + 8 gate-loads all in flight
    float4 v[8];
    float  gk[8];
#pragma unroll
    for (int k = 0; k < 8; k++) {
        v[k]  = __ldcs(xr + t + k * 256);
        gk[k] = grow[warp * 8 + (lane & 7) + k * 64];  // lanes 0..7 hold 8 chunks
    }
#pragma unroll
    for (int k = 0; k < 8; k++) {
        // lane l's chunk = warp*8 + (l>>2) + k*64 -> held by lane (l>>2)
        float gv = __shfl_sync(0xffffffffu, gk[k], lane >> 2);
        v[k].x *= gv; v[k].y *= gv; v[k].z *= gv; v[k].w *= gv;
        __stcs(orr + t + k * 256, v[k]);
    }
}

// ---------------------------------------------------------------------------
// kernel_launch: inputs in metadata order: x, gamma, w1, b1, w2, b2
// ---------------------------------------------------------------------------
extern "C" void kernel_launch(void* const* d_in, const int* in_sizes, int n_in,
                              void* d_out, int out_size)
{
    const float* x     = (const float*)d_in[0];
    const float* gamma = (const float*)d_in[1];
    const float* w1    = (const float*)d_in[2];
    const float* b1    = (const float*)d_in[3];
    const float* w2    = (const float*)d_in[4];
    const float* b2    = (const float*)d_in[5];
    float* out = (float*)d_out;

    transpose_w_kernel<<<(CC * CH) / 256, 256>>>(w1, w2);

    pool_ema_kernel<<<BB * CC, 256>>>(x, gamma);

    dim3 gridG(NN / NPG, BB);
    se_gate_kernel<<<gridG, 256>>>(b1, b2);

    apply_kernel<<<BB * CC, 256>>>(x, out);
}

// round 10
// speedup vs baseline: 1.9508x; 1.0381x over previous
#include <cuda_runtime.h>

// Problem constants (x[8,512,8192], CHUNK=16, SE 512->64->512)
#define BB   8
#define CC   512
#define LL   8192
#define CS   16
#define NN   (LL / CS)     // 512 chunk positions
#define CH   (CC / 8)      // 64 bottleneck channels
#define NPG  8             // chunk positions per block in the gate kernel

// Static device scratch (no allocs allowed).
__device__ float g_e   [(size_t)BB * CC * NN];   // EMA output, 8 MB
__device__ float g_gate[(size_t)BB * CC * NN];   // gate, 8 MB
__device__ float g_w1t [(size_t)CC * CH];        // w1 transposed [c][o], 128 KB
__device__ float g_w2t [(size_t)CH * CC];        // w2 transposed [k][c], 128 KB

// padded smem index: lane stride becomes 17 banks (conflict-free)
#define SPAD(i) ((i) + ((i) >> 4))

// ---------------------------------------------------------------------------
// Kernel 1: chunked mean pooling + causal EMA per (b, c) row.
// grid = B*C = 4096 blocks, 256 threads. Coalesced; 4-lane shfl chunk sums.
// Blocks 0..127 additionally transpose the SE weights (consumed only by the
// gate kernel, which launches after this kernel completes).
// ---------------------------------------------------------------------------
__global__ void __launch_bounds__(256) pool_ema_kernel(
    const float* __restrict__ x, const float* __restrict__ gamma,
    const float* __restrict__ w1, const float* __restrict__ w2)
{
    const int row = blockIdx.x;            // b*C + c
    const int c   = row & (CC - 1);
    const float g = gamma[c];
    const int t = threadIdx.x;

    // fold in the weight transpose (32768 elems each over 128 blocks)
    if (blockIdx.x < (CC * CH) / 256) {
        const int i = blockIdx.x * 256 + t;
        {   // w1 [CH][CC] -> w1t [CC][CH]
            int o = i / CC, cw = i % CC;
            g_w1t[(size_t)cw * CH + o] = w1[i];
        }
        {   // w2 [CC][CH] -> w2t [CH][CC]
            int cw = i / CH, k = i % CH;
            g_w2t[(size_t)k * CC + cw] = w2[i];
        }
    }

    __shared__ float s[NN + NN / 16];      // padded chunk means

    const float4* xr = reinterpret_cast<const float4*>(x) + (size_t)row * (LL / 4);

    float4 v[8];
#pragma unroll
    for (int k = 0; k < 8; k++)
        v[k] = xr[t + k * 256];            // 8 coalesced LDG.128 in flight

#pragma unroll
    for (int k = 0; k < 8; k++) {
        float r = (v[k].x + v[k].y) + (v[k].z + v[k].w);
        r += __shfl_down_sync(0xffffffffu, r, 2, 4);
        r += __shfl_down_sync(0xffffffffu, r, 1, 4);
        if ((t & 3) == 0) {
            int ci = (t >> 2) + k * 64;    // chunk index 0..511
            s[SPAD(ci)] = r * (1.0f / 16.0f);
        }
    }
    __syncthreads();

    if (t < 32) {
        const int lane = t;
        const float omg = 1.0f - g;

        float y = 0.f;
#pragma unroll
        for (int i = 0; i < 16; i++)
            y = fmaf(g, y, omg * s[lane * 17 + i]);      // SPAD(lane*16+i)
        float Bi = y;
        float g2 = g * g, g4 = g2 * g2, g8 = g4 * g4;
        float Ai = g8 * g8;

#pragma unroll
        for (int off = 1; off < 32; off <<= 1) {
            float a_up = __shfl_up_sync(0xffffffffu, Ai, off);
            float b_up = __shfl_up_sync(0xffffffffu, Bi, off);
            if (lane >= off) {
                Bi = fmaf(Ai, b_up, Bi);
                Ai = Ai * a_up;
            }
        }
        float prefix = __shfl_up_sync(0xffffffffu, Bi, 1);
        if (lane == 0) prefix = 0.f;

        float outv[16];
        y = prefix;
#pragma unroll
        for (int i = 0; i < 16; i++) {
            y = fmaf(g, y, omg * s[lane * 17 + i]);
            outv[i] = y;
        }
        float4* er = reinterpret_cast<float4*>(g_e + (size_t)row * NN + lane * 16);
#pragma unroll
        for (int i = 0; i < 4; i++)
            er[i] = make_float4(outv[4 * i], outv[4 * i + 1], outv[4 * i + 2], outv[4 * i + 3]);
    }
}

// ---------------------------------------------------------------------------
// Kernel 2: SE bottleneck -> sigmoid gate.
// grid (N/NPG = 64, B = 8) = 512 blocks, 512 THREADS (16 warps/block).
// GEMM1 K-dimension is split across 2 thread-halves (256 c each) with a smem
// reduce -> serial chain halved, 2x warps for latency hiding.
// GEMM2: one output channel per thread (no halves loop).
// ---------------------------------------------------------------------------
__global__ void __launch_bounds__(512) se_gate_kernel(
    const float* __restrict__ b1, const float* __restrict__ b2)
{
    const int b  = blockIdx.y;
    const int n0 = blockIdx.x * NPG;
    const int tid = threadIdx.x;

    __shared__ float es[CC][NPG];      // 16 KB e tile
    __shared__ float hp[2][CH][NPG];   // 4 KB partial hidden (then hp[0]=final)

    // ---- load e tile: 1024 float4 / 512 thr = 2 each ----
    const float4* ep = reinterpret_cast<const float4*>(
        g_e + ((size_t)b * CC) * NN + n0);
#pragma unroll
    for (int i = 0; i < 2; i++) {
        int idx = tid + i * 512;                 // = c*2 + q
        int cch = idx >> 1, q = idx & 1;
        float4 v = __ldcs(ep + (size_t)cch * (NN / 4) + q);
        *reinterpret_cast<float4*>(&es[cch][q * 4]) = v;
    }
    __syncthreads();

    // ---- GEMM1 partial: half = tid>>8 covers c in [half*256, half*256+256)
    //      thread (o = (tid&255)>>2, q = tid&3) -> j0 = q*2, 2 positions ----
    {
        const int half = tid >> 8;
        const int o = (tid & 255) >> 2, q = tid & 3;
        const int j0 = q * 2;
        const int c0 = half * 256;
        float a0 = 0.f, a1 = 0.f;
#pragma unroll 8
        for (int cc = c0; cc < c0 + 256; cc++) {
            float w = __ldg(g_w1t + (size_t)cc * CH + o);
            float2 e = *reinterpret_cast<const float2*>(&es[cc][j0]);
            a0 = fmaf(w, e.x, a0);
            a1 = fmaf(w, e.y, a1);
        }
        hp[half][o][j0 + 0] = a0;
        hp[half][o][j0 + 1] = a1;
    }
    __syncthreads();

    // ---- reduce halves + bias + relu (threads 0..255) ----
    if (tid < 256) {
        const int o = tid >> 2, q = tid & 3;
        const int j0 = q * 2;
        const float bb = b1[o];
        float h0 = hp[0][o][j0 + 0] + hp[1][o][j0 + 0] + bb;
        float h1 = hp[0][o][j0 + 1] + hp[1][o][j0 + 1] + bb;
        hp[0][o][j0 + 0] = fmaxf(h0, 0.f);
        hp[0][o][j0 + 1] = fmaxf(h1, 0.f);
    }
    __syncthreads();

    // ---- GEMM2: gate = sigmoid(W2 h + b2), one channel per thread ----
    {
        const int cch = tid;               // 0..511
        float acc[NPG];
#pragma unroll
        for (int j = 0; j < NPG; j++) acc[j] = 0.f;
#pragma unroll 8
        for (int k = 0; k < CH; k++) {
            float w = __ldg(g_w2t + (size_t)k * CC + cch);
            float4 h0 = *reinterpret_cast<const float4*>(&hp[0][k][0]);
            float4 h1 = *reinterpret_cast<const float4*>(&hp[0][k][4]);
            acc[0] = fmaf(w, h0.x, acc[0]); acc[1] = fmaf(w, h0.y, acc[1]);
            acc[2] = fmaf(w, h0.z, acc[2]); acc[3] = fmaf(w, h0.w, acc[3]);
            acc[4] = fmaf(w, h1.x, acc[4]); acc[5] = fmaf(w, h1.y, acc[5]);
            acc[6] = fmaf(w, h1.z, acc[6]); acc[7] = fmaf(w, h1.w, acc[7]);
        }
        const float bb = b2[cch];
        float4 o0, o1;
        o0.x = 1.0f / (1.0f + __expf(-(acc[0] + bb)));
        o0.y = 1.0f / (1.0f + __expf(-(acc[1] + bb)));
        o0.z = 1.0f / (1.0f + __expf(-(acc[2] + bb)));
        o0.w = 1.0f / (1.0f + __expf(-(acc[3] + bb)));
        o1.x = 1.0f / (1.0f + __expf(-(acc[4] + bb)));
        o1.y = 1.0f / (1.0f + __expf(-(acc[5] + bb)));
        o1.z = 1.0f / (1.0f + __expf(-(acc[6] + bb)));
        o1.w = 1.0f / (1.0f + __expf(-(acc[7] + bb)));
        float4* gp = reinterpret_cast<float4*>(
            g_gate + ((size_t)b * CC + cch) * NN + n0);
        gp[0] = o0;
        gp[1] = o1;
    }
}

// ---------------------------------------------------------------------------
// Kernel 3: out = gate * x, barrier-free pure stream.
// grid = 4096 blocks reversed vs pool. Gate distributed via shfl (no smem).
// x read-once (__ldcs), out streaming (__stcs).
// ---------------------------------------------------------------------------
__global__ void __launch_bounds__(256) apply_kernel(
    const float* __restrict__ x, float* __restrict__ out)
{
    const int row  = (BB * CC - 1) - blockIdx.x;      // reversed traversal
    const int t    = threadIdx.x;
    const int warp = t >> 5, lane = t & 31;

    const float* grow = g_gate + (size_t)row * NN;
    const float4* xr  = reinterpret_cast<const float4*>(x)  + (size_t)row * (LL / 4);
    float4*       orr = reinterpret_cast<float4*>(out)      + (size_t)row * (LL / 4);

    float4 v[8];
    float  gk[8];
#pragma unroll
    for (int k = 0; k < 8; k++) {
        v[k]  = __ldcs(xr + t + k * 256);
        gk[k] = grow[warp * 8 + (lane & 7) + k * 64];  // lanes 0..7 hold 8 chunks
    }
#pragma unroll
    for (int k = 0; k < 8; k++) {
        float gv = __shfl_sync(0xffffffffu, gk[k], lane >> 2);
        v[k].x *= gv; v[k].y *= gv; v[k].z *= gv; v[k].w *= gv;
        __stcs(orr + t + k * 256, v[k]);
    }
}

// ---------------------------------------------------------------------------
// kernel_launch: inputs in metadata order: x, gamma, w1, b1, w2, b2
// ---------------------------------------------------------------------------
extern "C" void kernel_launch(void* const* d_in, const int* in_sizes, int n_in,
                              void* d_out, int out_size)
{
    const float* x     = (const float*)d_in[0];
    const float* gamma = (const float*)d_in[1];
    const float* w1    = (const float*)d_in[2];
    const float* b1    = (const float*)d_in[3];
    const float* w2    = (const float*)d_in[4];
    const float* b2    = (const float*)d_in[5];
    float* out = (float*)d_out;

    pool_ema_kernel<<<BB * CC, 256>>>(x, gamma, w1, w2);

    dim3 gridG(NN / NPG, BB);
    se_gate_kernel<<<gridG, 512>>>(b1, b2);

    apply_kernel<<<BB * CC, 256>>>(x, out);
}